// round 13
// baseline (speedup 1.0000x reference)
#include <cuda_runtime.h>
#include <cuda_bf16.h>
#include <cuda_fp16.h>
#include <math.h>
#include <cstdint>

#define NN   50000
#define EE   800000
#define PP   65536
#define LDA  40

// ====================== scratch ======================

__device__ int   g_cnt[2 * NN + 64];      // [0,NN)=deg, [NN,2NN)=fill, [2NN,+64)=chain
__device__ float g_dn[NN];
__device__ int   g_rp[NN + 1];
__device__ __align__(16) int2 g_csr[EE];
__device__ __align__(16) float g_acc[NN * 128];
__device__ __align__(16) __half g_x16 [NN * 128];
__device__ __align__(16) __half g_hop1[NN * 128];
__device__ __align__(16) __half g_hop2[NN * 128];
__device__ __align__(16) __half g_hop3[NN * 128];
__device__ __align__(16) __half g_hA  [NN * 128];
__device__ __align__(16) __half g_hB  [NN * 128];
__device__ __align__(16) __half g_g   [NN * 256];
__device__ __align__(16) __half g_wt1[65536];
__device__ __align__(16) __half g_wt2[65536];
__device__ __align__(16) __half g_wt3[32768];

// ====================== helpers ======================

__device__ __forceinline__ uint32_t smem_u32(const void* p) {
    uint32_t a;
    asm("{ .reg .u64 t; cvta.to.shared.u64 t, %1; cvt.u32.u64 %0, t; }" : "=r"(a) : "l"(p));
    return a;
}

__device__ __forceinline__ void ldsm4(uint32_t* r, uint32_t addr) {
    asm volatile("ldmatrix.sync.aligned.m8n8.x4.shared.b16 {%0,%1,%2,%3}, [%4];"
                 : "=r"(r[0]), "=r"(r[1]), "=r"(r[2]), "=r"(r[3]) : "r"(addr));
}

__device__ __forceinline__ void mma16816f(float* c, const uint32_t* a, const uint32_t* b) {
    asm volatile(
        "mma.sync.aligned.m16n8k16.row.col.f32.f16.f16.f32 "
        "{%0,%1,%2,%3}, {%4,%5,%6,%7}, {%8,%9}, {%0,%1,%2,%3};"
        : "+f"(c[0]), "+f"(c[1]), "+f"(c[2]), "+f"(c[3])
        : "r"(a[0]), "r"(a[1]), "r"(a[2]), "r"(a[3]), "r"(b[0]), "r"(b[1]));
}

__device__ __forceinline__ void cpasync16(uint32_t saddr, const void* gptr) {
    asm volatile("cp.async.cg.shared.global [%0], [%1], 16;" :: "r"(saddr), "l"(gptr));
}
__device__ __forceinline__ void cpasync_commit() {
    asm volatile("cp.async.commit_group;" ::: "memory");
}
template <int N>
__device__ __forceinline__ void cpasync_wait() {
    asm volatile("cp.async.wait_group %0;" :: "n"(N) : "memory");
}

// ====================== prep + hist fused ======================

__global__ void k_prep2(const float* __restrict__ x,
                        const float* __restrict__ W1, const float* __restrict__ W2,
                        const float* __restrict__ W3, const int* __restrict__ dst) {
    int gid = blockIdx.x * 256 + threadIdx.x;
    if (gid < EE) atomicAdd(&g_cnt[dst[gid]], 1);
    if (gid < 65536) {
        int n = gid >> 9, k = gid & 511;
        g_wt1[gid] = __float2half_rn(W1[k * 128 + n]);
    } else if (gid < 131072) {
        int idx = gid - 65536;
        int n = idx >> 9, k = idx & 511;
        g_wt2[idx] = __float2half_rn(W2[k * 128 + n]);
    } else if (gid < 163840) {
        int idx = gid - 131072;
        int r = idx >> 7, k = idx & 127;
        int j = r >> 6, n = r & 63;
        g_wt3[idx] = __float2half_rn(W3[(j * 128 + k) * 64 + n]);
    }
    if (gid < NN * 32) {
        float4 v = __ldg((const float4*)x + gid);
        __half2 a = __floats2half2_rn(v.x, v.y);
        __half2 b = __floats2half2_rn(v.z, v.w);
        ((uint2*)g_x16)[gid] = make_uint2(*(uint32_t*)&a, *(uint32_t*)&b);
    }
}

// ====================== single-pass chained scan + dn ============

__global__ void __launch_bounds__(1024)
k_scanchain() {
    __shared__ int s[1024];
    __shared__ int sprev;
    volatile int* chain = (volatile int*)(g_cnt + 2 * NN);
    int b = blockIdx.x;
    int i = b * 1024 + threadIdx.x;
    int v = (i < NN) ? g_cnt[i] : 0;
    s[threadIdx.x] = v;
    __syncthreads();
    #pragma unroll
    for (int off = 1; off < 1024; off <<= 1) {
        int t = (threadIdx.x >= off) ? s[threadIdx.x - off] : 0;
        __syncthreads();
        s[threadIdx.x] += t;
        __syncthreads();
    }
    if (threadIdx.x == 0) {
        int prev = 0;
        if (b > 0) {
            int t;
            do { t = chain[b - 1]; } while (t == 0);
            prev = t - 1;
        }
        sprev = prev;
        __threadfence();
        chain[b] = prev + s[1023] + 1;
    }
    __syncthreads();
    int prev = sprev;
    if (i < NN) {
        g_rp[i + 1] = s[threadIdx.x] + prev;
        if (i == 0) g_rp[0] = 0;
        int d = (v < 1) ? 1 : v;
        g_dn[i] = rsqrtf((float)d);
    }
}

// ====================== scatter to interleaved CSR ================

__global__ void k_scatter(const int* __restrict__ src, const int* __restrict__ dst,
                          const float* __restrict__ w) {
    int e = blockIdx.x * blockDim.x + threadIdx.x;
    if (e >= EE) return;
    int s = src[e], d = dst[e];
    int slot = g_rp[d] + atomicAdd(&g_cnt[NN + d], 1);
    float cw = w[e] * g_dn[s] * g_dn[d];
    g_csr[slot] = make_int2(s, __float_as_int(cw));
}

// ====================== SpMM width 128 fp16, MLP-8 edge loop ================

__global__ void __launch_bounds__(256)
k_spmmh(const __half* __restrict__ fin, __half* __restrict__ fout) {
    int gw = (blockIdx.x * blockDim.x + threadIdx.x) >> 5;
    int lane = threadIdx.x & 31;
    if (gw >= NN) return;
    int beg = g_rp[gw], end = g_rp[gw + 1];
    const uint2* in = (const uint2*)fin;
    float4 acc = make_float4(0.f, 0.f, 0.f, 0.f);
    int e = beg;
    for (; e + 8 <= end; e += 8) {
        int2 p[8];
        uint2 v[8];
        #pragma unroll
        for (int q = 0; q < 8; q++) p[q] = __ldg(&g_csr[e + q]);
        #pragma unroll
        for (int q = 0; q < 8; q++) v[q] = __ldg(&in[(size_t)p[q].x * 32 + lane]);
        #pragma unroll
        for (int q = 0; q < 8; q++) {
            float w = __int_as_float(p[q].y);
            float2 f0 = __half22float2(*(__half2*)&v[q].x);
            float2 f1 = __half22float2(*(__half2*)&v[q].y);
            acc.x = fmaf(w, f0.x, acc.x);
            acc.y = fmaf(w, f0.y, acc.y);
            acc.z = fmaf(w, f1.x, acc.z);
            acc.w = fmaf(w, f1.y, acc.w);
        }
    }
    if (e + 4 <= end) {
        int2 p[4];
        uint2 v[4];
        #pragma unroll
        for (int q = 0; q < 4; q++) p[q] = __ldg(&g_csr[e + q]);
        #pragma unroll
        for (int q = 0; q < 4; q++) v[q] = __ldg(&in[(size_t)p[q].x * 32 + lane]);
        #pragma unroll
        for (int q = 0; q < 4; q++) {
            float w = __int_as_float(p[q].y);
            float2 f0 = __half22float2(*(__half2*)&v[q].x);
            float2 f1 = __half22float2(*(__half2*)&v[q].y);
            acc.x = fmaf(w, f0.x, acc.x);
            acc.y = fmaf(w, f0.y, acc.y);
            acc.z = fmaf(w, f1.x, acc.z);
            acc.w = fmaf(w, f1.y, acc.w);
        }
        e += 4;
    }
    for (; e < end; e++) {
        int2 p = __ldg(&g_csr[e]);
        float w = __int_as_float(p.y);
        uint2 v = __ldg(&in[(size_t)p.x * 32 + lane]);
        float2 f0 = __half22float2(*(__half2*)&v.x);
        float2 f1 = __half22float2(*(__half2*)&v.y);
        acc.x = fmaf(w, f0.x, acc.x);
        acc.y = fmaf(w, f0.y, acc.y);
        acc.z = fmaf(w, f1.x, acc.z);
        acc.w = fmaf(w, f1.y, acc.w);
    }
    __half2 o0 = __floats2half2_rn(acc.x, acc.y);
    __half2 o1 = __floats2half2_rn(acc.z, acc.w);
    ((uint2*)fout)[(size_t)gw * 32 + lane] = make_uint2(*(uint32_t*)&o0, *(uint32_t*)&o1);
}

// ====================== SpMM width 64 fp16, MLP-8, fused add ================

template <int F32OUT>
__global__ void __launch_bounds__(256)
k_spmm64h(const __half* __restrict__ fin, int sIn,
          const __half* __restrict__ addv, int sAdd,
          void* __restrict__ fout, int sOut) {
    int gw = (blockIdx.x * blockDim.x + threadIdx.x) >> 5;
    int lane = threadIdx.x & 31;
    if (gw >= NN) return;
    int beg = g_rp[gw], end = g_rp[gw + 1];
    float2 acc = make_float2(0.f, 0.f);
    int e = beg;
    for (; e + 8 <= end; e += 8) {
        int2 p[8];
        __half2 v[8];
        #pragma unroll
        for (int q = 0; q < 8; q++) p[q] = __ldg(&g_csr[e + q]);
        #pragma unroll
        for (int q = 0; q < 8; q++)
            v[q] = __ldg((const __half2*)(fin + (size_t)p[q].x * sIn) + lane);
        #pragma unroll
        for (int q = 0; q < 8; q++) {
            float w = __int_as_float(p[q].y);
            float2 f = __half22float2(v[q]);
            acc.x = fmaf(w, f.x, acc.x);
            acc.y = fmaf(w, f.y, acc.y);
        }
    }
    for (; e < end; e++) {
        int2 p = __ldg(&g_csr[e]);
        float w = __int_as_float(p.y);
        float2 v = __half22float2(__ldg((const __half2*)(fin + (size_t)p.x * sIn) + lane));
        acc.x = fmaf(w, v.x, acc.x);
        acc.y = fmaf(w, v.y, acc.y);
    }
    float2 a = __half22float2(__ldg((const __half2*)(addv + (size_t)gw * sAdd) + lane));
    acc.x += a.x; acc.y += a.y;
    if (F32OUT) {
        ((float2*)((float*)fout + (size_t)gw * sOut))[lane] = acc;
    } else {
        ((__half2*)((__half*)fout + (size_t)gw * sOut))[lane] = __floats2half2_rn(acc.x, acc.y);
    }
}

// ====================== partial GEMM chunk: g_acc (+)= f @ Wt[:,kOff:+128] ==
// 128x128 tile, K=128, runs on side stream concurrently with hops.

template <int FIRST>
__global__ void __launch_bounds__(256, 1)
k_pgemm(const __half* __restrict__ f, const __half* __restrict__ Wt, int kOff) {
    __shared__ __half As[2][128 * LDA];
    __shared__ __half Bs[2][128 * LDA];

    int tid = threadIdx.x, warp = tid >> 5, lane = tid & 31;
    int mw = warp & 1, nw = warp >> 1;
    int row0 = blockIdx.x * 128;
    int lr = tid >> 2, lj = tid & 3;
    int lr2 = (tid + 256) >> 2;

    float acc[4][4][4];
    #pragma unroll
    for (int i = 0; i < 4; i++)
        #pragma unroll
        for (int j = 0; j < 4; j++)
            #pragma unroll
            for (int q = 0; q < 4; q++) acc[i][j][q] = 0.f;

    auto load_stage = [&](int buf, int s) {
        uint32_t sA = smem_u32(&As[buf][0]);
        uint32_t sB = smem_u32(&Bs[buf][0]);
        int g0 = row0 + lr;  if (g0 > NN - 1) g0 = NN - 1;
        int g1 = row0 + lr2; if (g1 > NN - 1) g1 = NN - 1;
        cpasync16(sA + (uint32_t)(lr * LDA + lj * 8) * 2,
                  f + (size_t)g0 * 128 + s * 32 + lj * 8);
        cpasync16(sA + (uint32_t)(lr2 * LDA + lj * 8) * 2,
                  f + (size_t)g1 * 128 + s * 32 + lj * 8);
        cpasync16(sB + (uint32_t)(lr * LDA + lj * 8) * 2,
                  Wt + (size_t)lr * 512 + kOff + s * 32 + lj * 8);
        cpasync16(sB + (uint32_t)(lr2 * LDA + lj * 8) * 2,
                  Wt + (size_t)lr2 * 512 + kOff + s * 32 + lj * 8);
    };

    load_stage(0, 0);
    cpasync_commit();

    #pragma unroll 1
    for (int s = 0; s < 4; s++) {
        int buf = s & 1;
        cpasync_wait<0>();
        __syncthreads();
        if (s + 1 < 4) {
            load_stage(buf ^ 1, s + 1);
            cpasync_commit();
        }
        uint32_t sA = smem_u32(&As[buf][0]);
        uint32_t sB = smem_u32(&Bs[buf][0]);
        #pragma unroll
        for (int kk = 0; kk < 2; kk++) {
            int akoff = kk * 16 + ((lane >> 4) << 3);
            int lrow = lane & 15;
            uint32_t a[4][4];
            #pragma unroll
            for (int fi = 0; fi < 4; fi++) {
                uint32_t off = (uint32_t)(((64 * mw + 16 * fi + lrow) * LDA + akoff) * 2);
                ldsm4(a[fi], sA + off);
            }
            uint32_t b[4][2];
            #pragma unroll
            for (int fj2 = 0; fj2 < 2; fj2++) {
                uint32_t off = (uint32_t)(((32 * nw + 16 * fj2 + lrow) * LDA + akoff) * 2);
                uint32_t t[4];
                ldsm4(t, sB + off);
                b[2 * fj2][0] = t[0]; b[2 * fj2][1] = t[2];
                b[2 * fj2 + 1][0] = t[1]; b[2 * fj2 + 1][1] = t[3];
            }
            #pragma unroll
            for (int fi = 0; fi < 4; fi++)
                #pragma unroll
                for (int fj = 0; fj < 4; fj++)
                    mma16816f(acc[fi][fj], a[fi], b[fj]);
        }
        __syncthreads();
    }

    #pragma unroll
    for (int fi = 0; fi < 4; fi++) {
        #pragma unroll
        for (int fj = 0; fj < 4; fj++) {
            int mrow = row0 + 64 * mw + 16 * fi + (lane >> 2);
            int col  = 32 * nw + 8 * fj + 2 * (lane & 3);
            #pragma unroll
            for (int h = 0; h < 2; h++) {
                int r = mrow + 8 * h;
                if (r < NN) {
                    float2* p = (float2*)(g_acc + (size_t)r * 128 + col);
                    float2 v = make_float2(acc[fi][fj][2 * h + 0], acc[fi][fj][2 * h + 1]);
                    if (!FIRST) { float2 o = *p; v.x += o.x; v.y += o.y; }
                    *p = v;
                }
            }
        }
    }
}

// ====================== final GEMM: last chunk + acc + bias + relu ==========

__global__ void __launch_bounds__(256, 1)
k_mfinal(const __half* __restrict__ f, const __half* __restrict__ Wt, int kOff,
         const float* __restrict__ bias, __half* __restrict__ out) {
    __shared__ __half As[2][128 * LDA];
    __shared__ __half Bs[2][128 * LDA];

    int tid = threadIdx.x, warp = tid >> 5, lane = tid & 31;
    int mw = warp & 1, nw = warp >> 1;
    int row0 = blockIdx.x * 128;
    int lr = tid >> 2, lj = tid & 3;
    int lr2 = (tid + 256) >> 2;

    float acc[4][4][4];
    #pragma unroll
    for (int i = 0; i < 4; i++)
        #pragma unroll
        for (int j = 0; j < 4; j++)
            #pragma unroll
            for (int q = 0; q < 4; q++) acc[i][j][q] = 0.f;

    auto load_stage = [&](int buf, int s) {
        uint32_t sA = smem_u32(&As[buf][0]);
        uint32_t sB = smem_u32(&Bs[buf][0]);
        int g0 = row0 + lr;  if (g0 > NN - 1) g0 = NN - 1;
        int g1 = row0 + lr2; if (g1 > NN - 1) g1 = NN - 1;
        cpasync16(sA + (uint32_t)(lr * LDA + lj * 8) * 2,
                  f + (size_t)g0 * 128 + s * 32 + lj * 8);
        cpasync16(sA + (uint32_t)(lr2 * LDA + lj * 8) * 2,
                  f + (size_t)g1 * 128 + s * 32 + lj * 8);
        cpasync16(sB + (uint32_t)(lr * LDA + lj * 8) * 2,
                  Wt + (size_t)lr * 512 + kOff + s * 32 + lj * 8);
        cpasync16(sB + (uint32_t)(lr2 * LDA + lj * 8) * 2,
                  Wt + (size_t)lr2 * 512 + kOff + s * 32 + lj * 8);
    };

    load_stage(0, 0);
    cpasync_commit();

    #pragma unroll 1
    for (int s = 0; s < 4; s++) {
        int buf = s & 1;
        cpasync_wait<0>();
        __syncthreads();
        if (s + 1 < 4) {
            load_stage(buf ^ 1, s + 1);
            cpasync_commit();
        }
        uint32_t sA = smem_u32(&As[buf][0]);
        uint32_t sB = smem_u32(&Bs[buf][0]);
        #pragma unroll
        for (int kk = 0; kk < 2; kk++) {
            int akoff = kk * 16 + ((lane >> 4) << 3);
            int lrow = lane & 15;
            uint32_t a[4][4];
            #pragma unroll
            for (int fi = 0; fi < 4; fi++) {
                uint32_t off = (uint32_t)(((64 * mw + 16 * fi + lrow) * LDA + akoff) * 2);
                ldsm4(a[fi], sA + off);
            }
            uint32_t b[4][2];
            #pragma unroll
            for (int fj2 = 0; fj2 < 2; fj2++) {
                uint32_t off = (uint32_t)(((32 * nw + 16 * fj2 + lrow) * LDA + akoff) * 2);
                uint32_t t[4];
                ldsm4(t, sB + off);
                b[2 * fj2][0] = t[0]; b[2 * fj2][1] = t[2];
                b[2 * fj2 + 1][0] = t[1]; b[2 * fj2 + 1][1] = t[3];
            }
            #pragma unroll
            for (int fi = 0; fi < 4; fi++)
                #pragma unroll
                for (int fj = 0; fj < 4; fj++)
                    mma16816f(acc[fi][fj], a[fi], b[fj]);
        }
        __syncthreads();
    }

    #pragma unroll
    for (int fi = 0; fi < 4; fi++) {
        #pragma unroll
        for (int fj = 0; fj < 4; fj++) {
            int mrow = row0 + 64 * mw + 16 * fi + (lane >> 2);
            int col  = 32 * nw + 8 * fj + 2 * (lane & 3);
            #pragma unroll
            for (int h = 0; h < 2; h++) {
                int r = mrow + 8 * h;
                if (r < NN) {
                    float2 av = *(float2*)(g_acc + (size_t)r * 128 + col);
                    float v0 = acc[fi][fj][2 * h + 0] + av.x + bias[col];
                    float v1 = acc[fi][fj][2 * h + 1] + av.y + bias[col + 1];
                    v0 = v0 > 0.f ? v0 : 0.f;
                    v1 = v1 > 0.f ? v1 : 0.f;
                    *(__half2*)(out + (size_t)r * 128 + col) = __floats2half2_rn(v0, v1);
                }
            }
        }
    }
}

// ====================== layer-3 GEMM half (hB @ W3 rows rbase..rbase+128) ===

__global__ void __launch_bounds__(256, 1)
k_mgemm3(const __half* __restrict__ f, const __half* __restrict__ Wt, int rbase,
         const float* __restrict__ bias, __half* __restrict__ out) {
    __shared__ __half As[2][128 * LDA];
    __shared__ __half Bs[2][128 * LDA];

    int tid = threadIdx.x, warp = tid >> 5, lane = tid & 31;
    int mw = warp & 1, nw = warp >> 1;
    int row0 = blockIdx.x * 128;
    int lr = tid >> 2, lj = tid & 3;
    int lr2 = (tid + 256) >> 2;

    float acc[4][4][4];
    #pragma unroll
    for (int i = 0; i < 4; i++)
        #pragma unroll
        for (int j = 0; j < 4; j++)
            #pragma unroll
            for (int q = 0; q < 4; q++) acc[i][j][q] = 0.f;

    auto load_stage = [&](int buf, int s) {
        uint32_t sA = smem_u32(&As[buf][0]);
        uint32_t sB = smem_u32(&Bs[buf][0]);
        int g0 = row0 + lr;  if (g0 > NN - 1) g0 = NN - 1;
        int g1 = row0 + lr2; if (g1 > NN - 1) g1 = NN - 1;
        cpasync16(sA + (uint32_t)(lr * LDA + lj * 8) * 2,
                  f + (size_t)g0 * 128 + s * 32 + lj * 8);
        cpasync16(sA + (uint32_t)(lr2 * LDA + lj * 8) * 2,
                  f + (size_t)g1 * 128 + s * 32 + lj * 8);
        cpasync16(sB + (uint32_t)(lr * LDA + lj * 8) * 2,
                  Wt + (size_t)(rbase + lr) * 128 + s * 32 + lj * 8);
        cpasync16(sB + (uint32_t)(lr2 * LDA + lj * 8) * 2,
                  Wt + (size_t)(rbase + lr2) * 128 + s * 32 + lj * 8);
    };

    load_stage(0, 0);
    cpasync_commit();

    #pragma unroll 1
    for (int s = 0; s < 4; s++) {
        int buf = s & 1;
        cpasync_wait<0>();
        __syncthreads();
        if (s + 1 < 4) {
            load_stage(buf ^ 1, s + 1);
            cpasync_commit();
        }
        uint32_t sA = smem_u32(&As[buf][0]);
        uint32_t sB = smem_u32(&Bs[buf][0]);
        #pragma unroll
        for (int kk = 0; kk < 2; kk++) {
            int akoff = kk * 16 + ((lane >> 4) << 3);
            int lrow = lane & 15;
            uint32_t a[4][4];
            #pragma unroll
            for (int fi = 0; fi < 4; fi++) {
                uint32_t off = (uint32_t)(((64 * mw + 16 * fi + lrow) * LDA + akoff) * 2);
                ldsm4(a[fi], sA + off);
            }
            uint32_t b[4][2];
            #pragma unroll
            for (int fj2 = 0; fj2 < 2; fj2++) {
                uint32_t off = (uint32_t)(((32 * nw + 16 * fj2 + lrow) * LDA + akoff) * 2);
                uint32_t t[4];
                ldsm4(t, sB + off);
                b[2 * fj2][0] = t[0]; b[2 * fj2][1] = t[2];
                b[2 * fj2 + 1][0] = t[1]; b[2 * fj2 + 1][1] = t[3];
            }
            #pragma unroll
            for (int fi = 0; fi < 4; fi++)
                #pragma unroll
                for (int fj = 0; fj < 4; fj++)
                    mma16816f(acc[fi][fj], a[fi], b[fj]);
        }
        __syncthreads();
    }

    #pragma unroll
    for (int fi = 0; fi < 4; fi++) {
        #pragma unroll
        for (int fj = 0; fj < 4; fj++) {
            int mrow = row0 + 64 * mw + 16 * fi + (lane >> 2);
            int col  = 32 * nw + 8 * fj + 2 * (lane & 3);
            #pragma unroll
            for (int h = 0; h < 2; h++) {
                int r = mrow + 8 * h;
                if (r < NN) {
                    int cg = rbase + col;
                    float v0 = acc[fi][fj][2 * h + 0];
                    float v1 = acc[fi][fj][2 * h + 1];
                    if (cg < 64) { v0 += bias[cg]; v1 += bias[cg + 1]; }
                    *(__half2*)(out + (size_t)r * 256 + cg) = __floats2half2_rn(v0, v1);
                }
            }
        }
    }
}

// ====================== predictor MLP ======================

__global__ void __launch_bounds__(256)
k_pred(const int* __restrict__ ps, const int* __restrict__ pd,
       const int* __restrict__ ns, const int* __restrict__ nd,
       const float* __restrict__ h,
       const float* __restrict__ P1, const float* __restrict__ pb1,
       const float* __restrict__ P2, const float* __restrict__ pb2,
       const float* __restrict__ P3, const float* __restrict__ pb3,
       float* __restrict__ out) {
    __shared__ float zs[8][64];
    __shared__ float a1s[8][32];
    int warp = (blockIdx.x * blockDim.x + threadIdx.x) >> 5;
    int lane = threadIdx.x & 31;
    int wl   = (threadIdx.x >> 5) & 7;
    if (warp >= 2 * PP) return;
    int s, d;
    if (warp < PP) { s = ps[warp]; d = pd[warp]; }
    else           { s = ns[warp - PP]; d = nd[warp - PP]; }

    const float* hs = h + (size_t)s * 64;
    const float* hd = h + (size_t)d * 64;
    zs[wl][lane]      = hs[lane]      * hd[lane];
    zs[wl][lane + 32] = hs[lane + 32] * hd[lane + 32];
    __syncwarp();

    float a = pb1[lane];
    #pragma unroll
    for (int k = 0; k < 64; k++) a = fmaf(zs[wl][k], P1[k * 32 + lane], a);
    a = a > 0.f ? a : 0.2f * a;
    a1s[wl][lane] = a;
    __syncwarp();

    float v = 0.f;
    if (lane < 16) {
        v = pb2[lane];
        #pragma unroll
        for (int k = 0; k < 32; k++) v = fmaf(a1s[wl][k], P2[k * 16 + lane], v);
        v = v > 0.f ? v : 0.2f * v;
        v *= P3[lane];
    }
    #pragma unroll
    for (int off = 8; off; off >>= 1) v += __shfl_down_sync(0xffffffffu, v, off);
    if (lane == 0) out[warp] = v + pb3[0];
}

// ====================== host ======================

extern "C" void kernel_launch(void* const* d_in, const int* in_sizes, int n_in,
                              void* d_out, int out_size) {
    const float* x       = (const float*)d_in[0];
    const int*   src     = (const int*)d_in[1];
    const int*   dst     = (const int*)d_in[2];
    const float* w_edge  = (const float*)d_in[3];
    const int*   pos_src = (const int*)d_in[4];
    const int*   pos_dst = (const int*)d_in[5];
    const int*   neg_src = (const int*)d_in[6];
    const int*   neg_dst = (const int*)d_in[7];
    const float* W1 = (const float*)d_in[8];
    const float* b1 = (const float*)d_in[9];
    const float* W2 = (const float*)d_in[10];
    const float* b2 = (const float*)d_in[11];
    const float* W3 = (const float*)d_in[12];
    const float* b3 = (const float*)d_in[13];
    const float* P1 = (const float*)d_in[14];
    const float* pb1 = (const float*)d_in[15];
    const float* P2 = (const float*)d_in[16];
    const float* pb2 = (const float*)d_in[17];
    const float* P3 = (const float*)d_in[18];
    const float* pb3 = (const float*)d_in[19];
    float* out = (float*)d_out;

    static cudaStream_t side = nullptr;
    static cudaEvent_t ev[10];
    if (side == nullptr) {
        cudaStreamCreateWithFlags(&side, cudaStreamNonBlocking);
        for (int i = 0; i < 10; i++)
            cudaEventCreateWithFlags(&ev[i], cudaEventDisableTiming);
    }

    void *p_cnt, *p_x16, *p_hop1, *p_hop2, *p_hop3, *p_hA, *p_hB, *p_g;
    void *p_w1, *p_w2, *p_w3;
    cudaGetSymbolAddress(&p_cnt,  g_cnt);
    cudaGetSymbolAddress(&p_x16,  g_x16);
    cudaGetSymbolAddress(&p_hop1, g_hop1);
    cudaGetSymbolAddress(&p_hop2, g_hop2);
    cudaGetSymbolAddress(&p_hop3, g_hop3);
    cudaGetSymbolAddress(&p_hA,   g_hA);
    cudaGetSymbolAddress(&p_hB,   g_hB);
    cudaGetSymbolAddress(&p_g,    g_g);
    cudaGetSymbolAddress(&p_w1,   g_wt1);
    cudaGetSymbolAddress(&p_w2,   g_wt2);
    cudaGetSymbolAddress(&p_w3,   g_wt3);
    __half* x16  = (__half*)p_x16;
    __half* hop1 = (__half*)p_hop1;
    __half* hop2 = (__half*)p_hop2;
    __half* hop3 = (__half*)p_hop3;
    __half* hA   = (__half*)p_hA;
    __half* hB   = (__half*)p_hB;
    __half* gg   = (__half*)p_g;
    __half* w1   = (__half*)p_w1;
    __half* w2   = (__half*)p_w2;
    __half* w3   = (__half*)p_w3;
    float* hfin = out + 2 * PP;

    const int EB = (EE + 255) / 256;
    const int WG = (NN * 32 + 255) / 256;
    const int MT = (NN + 127) / 128;

    // ---- preprocessing (main stream 0) ----
    cudaMemsetAsync(p_cnt, 0, (2 * NN + 64) * sizeof(int));
    k_prep2<<<(NN * 32 + 255) / 256, 256>>>(x, W1, W2, W3, dst);
    cudaEventRecord(ev[0], 0);                       // x16 + weights ready
    k_scanchain<<<(NN + 1023) / 1024, 1024>>>();
    k_scatter<<<EB, 256>>>(src, dst, w_edge);

    // ---- layer 1 ----
    cudaStreamWaitEvent(side, ev[0], 0);
    k_pgemm<1><<<MT, 256, 0, side>>>(x16, w1, 0);    // g0 overlaps scan/scatter/hop1
    k_spmmh<<<WG, 256>>>(x16, hop1);
    cudaEventRecord(ev[1], 0);
    cudaStreamWaitEvent(side, ev[1], 0);
    k_pgemm<0><<<MT, 256, 0, side>>>(hop1, w1, 128); // g1 overlaps hop2
    k_spmmh<<<WG, 256>>>(hop1, hop2);
    cudaEventRecord(ev[2], 0);
    cudaStreamWaitEvent(side, ev[2], 0);
    k_pgemm<0><<<MT, 256, 0, side>>>(hop2, w1, 256); // g2 overlaps hop3
    cudaEventRecord(ev[3], side);
    k_spmmh<<<WG, 256>>>(hop2, hop3);
    cudaStreamWaitEvent(0, ev[3], 0);                // join side before reading g_acc
    k_mfinal<<<MT, 256>>>(hop3, w1, 384, b1, hA);

    // ---- layer 2 ----
    cudaEventRecord(ev[4], 0);                       // hA ready
    cudaStreamWaitEvent(side, ev[4], 0);
    k_pgemm<1><<<MT, 256, 0, side>>>(hA, w2, 0);
    k_spmmh<<<WG, 256>>>(hA, hop1);
    cudaEventRecord(ev[5], 0);
    cudaStreamWaitEvent(side, ev[5], 0);
    k_pgemm<0><<<MT, 256, 0, side>>>(hop1, w2, 128);
    k_spmmh<<<WG, 256>>>(hop1, hop2);
    cudaEventRecord(ev[6], 0);
    cudaStreamWaitEvent(side, ev[6], 0);
    k_pgemm<0><<<MT, 256, 0, side>>>(hop2, w2, 256);
    cudaEventRecord(ev[7], side);
    k_spmmh<<<WG, 256>>>(hop2, hop3);
    cudaStreamWaitEvent(0, ev[7], 0);
    k_mfinal<<<MT, 256>>>(hop3, w2, 384, b2, hB);

    // ---- layer 3 (Horner); split GEMM, low half on side stream ----
    cudaEventRecord(ev[8], 0);                       // hB ready
    cudaStreamWaitEvent(side, ev[8], 0);
    k_mgemm3<<<MT, 256, 0, side>>>(hB, w3, 0, b3, gg);   // chunks 0,1
    cudaEventRecord(ev[9], side);
    k_mgemm3<<<MT, 256>>>(hB, w3, 128, b3, gg);          // chunks 2,3 (main)
    k_spmm64h<0><<<WG, 256>>>(gg + 192, 256, gg + 128, 256, hop1, 64);
    cudaStreamWaitEvent(0, ev[9], 0);                // need chunk1 (gg+64) next
    k_spmm64h<0><<<WG, 256>>>(hop1, 64,    gg + 64,  256, hop2, 64);
    k_spmm64h<1><<<WG, 256>>>(hop2, 64,    gg,       256, hfin, 64);

    // ---- predictor ----
    k_pred<<<(2 * PP) / 8, 256>>>(pos_src, pos_dst, neg_src, neg_dst, hfin,
                                  P1, pb1, P2, pb2, P3, pb3, out);
}

// round 15
// speedup vs baseline: 1.1472x; 1.1472x over previous
#include <cuda_runtime.h>
#include <cuda_bf16.h>
#include <cuda_fp16.h>
#include <math.h>
#include <cstdint>

#define NN   50000
#define EE   800000
#define PP   65536
#define LDA  40

// ====================== scratch ======================

__device__ int   g_deg[NN];
__device__ float g_dn[NN];
__device__ int   g_rp[NN + 1];
__device__ int   g_fill[NN];
__device__ volatile int g_chain[64];
__device__ __align__(16) int2 g_csr[EE];
__device__ __align__(16) __half g_x16 [NN * 128];
__device__ __align__(16) __half g_hop1[NN * 128];
__device__ __align__(16) __half g_hop2[NN * 128];
__device__ __align__(16) __half g_hop3[NN * 128];
__device__ __align__(16) __half g_hA  [NN * 128];
__device__ __align__(16) __half g_hB  [NN * 128];
__device__ __align__(16) __half g_g   [NN * 256];
__device__ __align__(16) __half g_wt1[65536];
__device__ __align__(16) __half g_wt2[65536];
__device__ __align__(16) __half g_wt3[32768];

// ====================== helpers ======================

__device__ __forceinline__ uint32_t smem_u32(const void* p) {
    uint32_t a;
    asm("{ .reg .u64 t; cvta.to.shared.u64 t, %1; cvt.u32.u64 %0, t; }" : "=r"(a) : "l"(p));
    return a;
}

__device__ __forceinline__ void ldsm4(uint32_t* r, uint32_t addr) {
    asm volatile("ldmatrix.sync.aligned.m8n8.x4.shared.b16 {%0,%1,%2,%3}, [%4];"
                 : "=r"(r[0]), "=r"(r[1]), "=r"(r[2]), "=r"(r[3]) : "r"(addr));
}

__device__ __forceinline__ void mma16816f(float* c, const uint32_t* a, const uint32_t* b) {
    asm volatile(
        "mma.sync.aligned.m16n8k16.row.col.f32.f16.f16.f32 "
        "{%0,%1,%2,%3}, {%4,%5,%6,%7}, {%8,%9}, {%0,%1,%2,%3};"
        : "+f"(c[0]), "+f"(c[1]), "+f"(c[2]), "+f"(c[3])
        : "r"(a[0]), "r"(a[1]), "r"(a[2]), "r"(a[3]), "r"(b[0]), "r"(b[1]));
}

__device__ __forceinline__ void cpasync16(uint32_t saddr, const void* gptr) {
    asm volatile("cp.async.cg.shared.global [%0], [%1], 16;" :: "r"(saddr), "l"(gptr));
}
__device__ __forceinline__ void cpasync_commit() {
    asm volatile("cp.async.commit_group;" ::: "memory");
}
template <int N>
__device__ __forceinline__ void cpasync_wait() {
    asm volatile("cp.async.wait_group %0;" :: "n"(N) : "memory");
}

// ====================== launch 1: fused preprocessing ======================
// zeros deg/fill/chain, converts x -> fp16, transposes + converts weights

__global__ void k_prepall(const float* __restrict__ x,
                          const float* __restrict__ W1, const float* __restrict__ W2,
                          const float* __restrict__ W3) {
    int gid = blockIdx.x * 256 + threadIdx.x;
    if (gid < NN) { g_deg[gid] = 0; g_fill[gid] = 0; }
    if (gid < 64) g_chain[gid] = 0;
    if (gid < 65536) {
        int n = gid >> 9, k = gid & 511;
        g_wt1[gid] = __float2half_rn(W1[k * 128 + n]);
    } else if (gid < 131072) {
        int idx = gid - 65536;
        int n = idx >> 9, k = idx & 511;
        g_wt2[idx] = __float2half_rn(W2[k * 128 + n]);
    } else if (gid < 163840) {
        int idx = gid - 131072;
        int r = idx >> 7, k = idx & 127;
        int j = r >> 6, n = r & 63;
        g_wt3[idx] = __float2half_rn(W3[(j * 128 + k) * 64 + n]);
    }
    if (gid < NN * 32) {
        float4 v = __ldg((const float4*)x + gid);
        __half2 a = __floats2half2_rn(v.x, v.y);
        __half2 b = __floats2half2_rn(v.z, v.w);
        ((uint2*)g_x16)[gid] = make_uint2(*(uint32_t*)&a, *(uint32_t*)&b);
    }
}

// ====================== launch 2: degree histogram ======================

__global__ void k_hist(const int* __restrict__ dst) {
    int e = blockIdx.x * blockDim.x + threadIdx.x;
    if (e < EE) atomicAdd(&g_deg[dst[e]], 1);
}

// ====================== launch 3: single-pass chained scan + dn ============

__global__ void __launch_bounds__(1024)
k_scanchain() {
    __shared__ int s[1024];
    __shared__ int sprev;
    int b = blockIdx.x;
    int i = b * 1024 + threadIdx.x;
    int v = (i < NN) ? g_deg[i] : 0;
    s[threadIdx.x] = v;
    __syncthreads();
    #pragma unroll
    for (int off = 1; off < 1024; off <<= 1) {
        int t = (threadIdx.x >= off) ? s[threadIdx.x - off] : 0;
        __syncthreads();
        s[threadIdx.x] += t;
        __syncthreads();
    }
    if (threadIdx.x == 0) {
        int prev = 0;
        if (b > 0) {
            int t;
            do { t = g_chain[b - 1]; } while (t == 0);
            prev = t - 1;
        }
        sprev = prev;
        __threadfence();
        g_chain[b] = prev + s[1023] + 1;
    }
    __syncthreads();
    int prev = sprev;
    if (i < NN) {
        g_rp[i + 1] = s[threadIdx.x] + prev;
        if (i == 0) g_rp[0] = 0;
        int d = (v < 1) ? 1 : v;
        g_dn[i] = rsqrtf((float)d);
    }
}

// ====================== launch 4: scatter to interleaved CSR ================

__global__ void k_scatter(const int* __restrict__ src, const int* __restrict__ dst,
                          const float* __restrict__ w) {
    int e = blockIdx.x * blockDim.x + threadIdx.x;
    if (e >= EE) return;
    int s = src[e], d = dst[e];
    int slot = g_rp[d] + atomicAdd(&g_fill[d], 1);
    float cw = w[e] * g_dn[s] * g_dn[d];
    g_csr[slot] = make_int2(s, __float_as_int(cw));
}

// ====================== SpMM width 128 fp16, MLP-4 edge loop ================
// __launch_bounds__(256, 8): force <=32 regs so 64 warps/SM fit (full occ)

__global__ void __launch_bounds__(256, 8)
k_spmmh(const __half* __restrict__ fin, __half* __restrict__ fout) {
    int gw = (blockIdx.x * blockDim.x + threadIdx.x) >> 5;
    int lane = threadIdx.x & 31;
    if (gw >= NN) return;
    int beg = g_rp[gw], end = g_rp[gw + 1];
    const uint2* in = (const uint2*)fin;
    float4 acc = make_float4(0.f, 0.f, 0.f, 0.f);
    int e = beg;
    for (; e + 4 <= end; e += 4) {
        int2 p0 = __ldg(&g_csr[e + 0]);
        int2 p1 = __ldg(&g_csr[e + 1]);
        int2 p2 = __ldg(&g_csr[e + 2]);
        int2 p3 = __ldg(&g_csr[e + 3]);
        uint2 v0 = __ldg(&in[(size_t)p0.x * 32 + lane]);
        uint2 v1 = __ldg(&in[(size_t)p1.x * 32 + lane]);
        uint2 v2 = __ldg(&in[(size_t)p2.x * 32 + lane]);
        uint2 v3 = __ldg(&in[(size_t)p3.x * 32 + lane]);
        float w0 = __int_as_float(p0.y), w1 = __int_as_float(p1.y);
        float w2 = __int_as_float(p2.y), w3 = __int_as_float(p3.y);
        float2 a0 = __half22float2(*(__half2*)&v0.x), b0 = __half22float2(*(__half2*)&v0.y);
        float2 a1 = __half22float2(*(__half2*)&v1.x), b1 = __half22float2(*(__half2*)&v1.y);
        float2 a2 = __half22float2(*(__half2*)&v2.x), b2 = __half22float2(*(__half2*)&v2.y);
        float2 a3 = __half22float2(*(__half2*)&v3.x), b3 = __half22float2(*(__half2*)&v3.y);
        acc.x = fmaf(w0, a0.x, acc.x); acc.y = fmaf(w0, a0.y, acc.y);
        acc.z = fmaf(w0, b0.x, acc.z); acc.w = fmaf(w0, b0.y, acc.w);
        acc.x = fmaf(w1, a1.x, acc.x); acc.y = fmaf(w1, a1.y, acc.y);
        acc.z = fmaf(w1, b1.x, acc.z); acc.w = fmaf(w1, b1.y, acc.w);
        acc.x = fmaf(w2, a2.x, acc.x); acc.y = fmaf(w2, a2.y, acc.y);
        acc.z = fmaf(w2, b2.x, acc.z); acc.w = fmaf(w2, b2.y, acc.w);
        acc.x = fmaf(w3, a3.x, acc.x); acc.y = fmaf(w3, a3.y, acc.y);
        acc.z = fmaf(w3, b3.x, acc.z); acc.w = fmaf(w3, b3.y, acc.w);
    }
    for (; e < end; e++) {
        int2 p = __ldg(&g_csr[e]);
        float w = __int_as_float(p.y);
        uint2 v = __ldg(&in[(size_t)p.x * 32 + lane]);
        float2 f0 = __half22float2(*(__half2*)&v.x);
        float2 f1 = __half22float2(*(__half2*)&v.y);
        acc.x = fmaf(w, f0.x, acc.x);
        acc.y = fmaf(w, f0.y, acc.y);
        acc.z = fmaf(w, f1.x, acc.z);
        acc.w = fmaf(w, f1.y, acc.w);
    }
    __half2 o0 = __floats2half2_rn(acc.x, acc.y);
    __half2 o1 = __floats2half2_rn(acc.z, acc.w);
    ((uint2*)fout)[(size_t)gw * 32 + lane] = make_uint2(*(uint32_t*)&o0, *(uint32_t*)&o1);
}

// ====================== SpMM width 64 fp16, MLP-4, fused add ================

template <int F32OUT>
__global__ void __launch_bounds__(256, 8)
k_spmm64h(const __half* __restrict__ fin, int sIn,
          const __half* __restrict__ addv, int sAdd,
          void* __restrict__ fout, int sOut) {
    int gw = (blockIdx.x * blockDim.x + threadIdx.x) >> 5;
    int lane = threadIdx.x & 31;
    if (gw >= NN) return;
    int beg = g_rp[gw], end = g_rp[gw + 1];
    float2 acc = make_float2(0.f, 0.f);
    int e = beg;
    for (; e + 4 <= end; e += 4) {
        int2 p0 = __ldg(&g_csr[e + 0]);
        int2 p1 = __ldg(&g_csr[e + 1]);
        int2 p2 = __ldg(&g_csr[e + 2]);
        int2 p3 = __ldg(&g_csr[e + 3]);
        __half2 h0 = __ldg((const __half2*)(fin + (size_t)p0.x * sIn) + lane);
        __half2 h1 = __ldg((const __half2*)(fin + (size_t)p1.x * sIn) + lane);
        __half2 h2 = __ldg((const __half2*)(fin + (size_t)p2.x * sIn) + lane);
        __half2 h3 = __ldg((const __half2*)(fin + (size_t)p3.x * sIn) + lane);
        float2 v0 = __half22float2(h0), v1 = __half22float2(h1);
        float2 v2 = __half22float2(h2), v3 = __half22float2(h3);
        float w0 = __int_as_float(p0.y), w1 = __int_as_float(p1.y);
        float w2 = __int_as_float(p2.y), w3 = __int_as_float(p3.y);
        acc.x = fmaf(w0, v0.x, acc.x); acc.y = fmaf(w0, v0.y, acc.y);
        acc.x = fmaf(w1, v1.x, acc.x); acc.y = fmaf(w1, v1.y, acc.y);
        acc.x = fmaf(w2, v2.x, acc.x); acc.y = fmaf(w2, v2.y, acc.y);
        acc.x = fmaf(w3, v3.x, acc.x); acc.y = fmaf(w3, v3.y, acc.y);
    }
    for (; e < end; e++) {
        int2 p = __ldg(&g_csr[e]);
        float w = __int_as_float(p.y);
        float2 v = __half22float2(__ldg((const __half2*)(fin + (size_t)p.x * sIn) + lane));
        acc.x = fmaf(w, v.x, acc.x);
        acc.y = fmaf(w, v.y, acc.y);
    }
    float2 a = __half22float2(__ldg((const __half2*)(addv + (size_t)gw * sAdd) + lane));
    acc.x += a.x; acc.y += a.y;
    if (F32OUT) {
        ((float2*)((float*)fout + (size_t)gw * sOut))[lane] = acc;
    } else {
        ((__half2*)((__half*)fout + (size_t)gw * sOut))[lane] = __floats2half2_rn(acc.x, acc.y);
    }
}

// ====================== fp16 HMMA GEMM, cp.async 2-stage pipeline ==========
// CTA tile 128x128; 8 warps 2(M)x4(N); warp tile 64x32.
// MODE 0: out = relu(d + bias[c]) fp16, grid.y=1
// MODE 1: out[r*256+by*128+c] = d + (col<64 ? bias[col] : 0) fp16, grid.y=2

template <int KTOT, int MODE>
__global__ void __launch_bounds__(256, 1)
k_mgemm(const __half* __restrict__ f0, const __half* __restrict__ f1,
        const __half* __restrict__ f2, const __half* __restrict__ f3,
        const __half* __restrict__ Wt,
        const float* __restrict__ bias, __half* __restrict__ out) {
    __shared__ __half As[2][128 * LDA];
    __shared__ __half Bs[2][128 * LDA];

    const __half* bases[4] = {f0, f1, f2, f3};
    int tid = threadIdx.x, warp = tid >> 5, lane = tid & 31;
    int mw = warp & 1, nw = warp >> 1;
    int row0 = blockIdx.x * 128;
    int rbase = (MODE == 1) ? blockIdx.y * 128 : 0;

    int ar0 = tid >> 2, aj0 = tid & 3;
    int ar1 = (tid + 256) >> 2, aj1 = tid & 3;

    float acc[4][4][4];
    #pragma unroll
    for (int i = 0; i < 4; i++)
        #pragma unroll
        for (int j = 0; j < 4; j++)
            #pragma unroll
            for (int q = 0; q < 4; q++) acc[i][j][q] = 0.f;

    const int NSTEP = KTOT / 32;

    auto load_stage = [&](int buf, int s) {
        const __half* Ab = bases[(s * 32) >> 7];
        int coloff = (s * 32) & 127;
        uint32_t sA = smem_u32(&As[buf][0]);
        uint32_t sB = smem_u32(&Bs[buf][0]);
        int g0 = row0 + ar0; if (g0 > NN - 1) g0 = NN - 1;
        int g1 = row0 + ar1; if (g1 > NN - 1) g1 = NN - 1;
        cpasync16(sA + (uint32_t)(ar0 * LDA + aj0 * 8) * 2,
                  Ab + (size_t)g0 * 128 + coloff + aj0 * 8);
        cpasync16(sA + (uint32_t)(ar1 * LDA + aj1 * 8) * 2,
                  Ab + (size_t)g1 * 128 + coloff + aj1 * 8);
        cpasync16(sB + (uint32_t)(ar0 * LDA + aj0 * 8) * 2,
                  Wt + (size_t)(rbase + ar0) * KTOT + s * 32 + aj0 * 8);
        cpasync16(sB + (uint32_t)(ar1 * LDA + aj1 * 8) * 2,
                  Wt + (size_t)(rbase + ar1) * KTOT + s * 32 + aj1 * 8);
    };

    load_stage(0, 0);
    cpasync_commit();

    #pragma unroll 1
    for (int s = 0; s < NSTEP; s++) {
        int buf = s & 1;
        cpasync_wait<0>();
        __syncthreads();
        if (s + 1 < NSTEP) {
            load_stage(buf ^ 1, s + 1);
            cpasync_commit();
        }

        uint32_t sA = smem_u32(&As[buf][0]);
        uint32_t sB = smem_u32(&Bs[buf][0]);
        #pragma unroll
        for (int kk = 0; kk < 2; kk++) {
            int akoff = kk * 16 + ((lane >> 4) << 3);
            int lrow = lane & 15;
            uint32_t a[4][4];
            #pragma unroll
            for (int fi = 0; fi < 4; fi++) {
                uint32_t off = (uint32_t)(((64 * mw + 16 * fi + lrow) * LDA + akoff) * 2);
                ldsm4(a[fi], sA + off);
            }
            uint32_t b[4][2];
            #pragma unroll
            for (int fj2 = 0; fj2 < 2; fj2++) {
                uint32_t off = (uint32_t)(((32 * nw + 16 * fj2 + lrow) * LDA + akoff) * 2);
                uint32_t t[4];
                ldsm4(t, sB + off);
                b[2 * fj2][0] = t[0]; b[2 * fj2][1] = t[2];
                b[2 * fj2 + 1][0] = t[1]; b[2 * fj2 + 1][1] = t[3];
            }
            #pragma unroll
            for (int fi = 0; fi < 4; fi++)
                #pragma unroll
                for (int fj = 0; fj < 4; fj++)
                    mma16816f(acc[fi][fj], a[fi], b[fj]);
        }
        __syncthreads();
    }

    #pragma unroll
    for (int fi = 0; fi < 4; fi++) {
        #pragma unroll
        for (int fj = 0; fj < 4; fj++) {
            int mrow = row0 + 64 * mw + 16 * fi + (lane >> 2);
            int col  = 32 * nw + 8 * fj + 2 * (lane & 3);
            #pragma unroll
            for (int h = 0; h < 2; h++) {
                int r = mrow + 8 * h;
                if (r < NN) {
                    float v0 = acc[fi][fj][2 * h + 0];
                    float v1 = acc[fi][fj][2 * h + 1];
                    if (MODE == 0) {
                        v0 += bias[col];     v1 += bias[col + 1];
                        v0 = v0 > 0.f ? v0 : 0.f;
                        v1 = v1 > 0.f ? v1 : 0.f;
                        *(__half2*)(out + (size_t)r * 128 + col) = __floats2half2_rn(v0, v1);
                    } else {
                        int cg = blockIdx.y * 128 + col;
                        if (cg < 64) { v0 += bias[cg]; v1 += bias[cg + 1]; }
                        *(__half2*)(out + (size_t)r * 256 + cg) = __floats2half2_rn(v0, v1);
                    }
                }
            }
        }
    }
}

// ====================== predictor MLP ======================

__global__ void __launch_bounds__(256)
k_pred(const int* __restrict__ ps, const int* __restrict__ pd,
       const int* __restrict__ ns, const int* __restrict__ nd,
       const float* __restrict__ h,
       const float* __restrict__ P1, const float* __restrict__ pb1,
       const float* __restrict__ P2, const float* __restrict__ pb2,
       const float* __restrict__ P3, const float* __restrict__ pb3,
       float* __restrict__ out) {
    __shared__ float zs[8][64];
    __shared__ float a1s[8][32];
    int warp = (blockIdx.x * blockDim.x + threadIdx.x) >> 5;
    int lane = threadIdx.x & 31;
    int wl   = (threadIdx.x >> 5) & 7;
    if (warp >= 2 * PP) return;
    int s, d;
    if (warp < PP) { s = ps[warp]; d = pd[warp]; }
    else           { s = ns[warp - PP]; d = nd[warp - PP]; }

    const float* hs = h + (size_t)s * 64;
    const float* hd = h + (size_t)d * 64;
    zs[wl][lane]      = hs[lane]      * hd[lane];
    zs[wl][lane + 32] = hs[lane + 32] * hd[lane + 32];
    __syncwarp();

    float a = pb1[lane];
    #pragma unroll
    for (int k = 0; k < 64; k++) a = fmaf(zs[wl][k], P1[k * 32 + lane], a);
    a = a > 0.f ? a : 0.2f * a;
    a1s[wl][lane] = a;
    __syncwarp();

    float v = 0.f;
    if (lane < 16) {
        v = pb2[lane];
        #pragma unroll
        for (int k = 0; k < 32; k++) v = fmaf(a1s[wl][k], P2[k * 16 + lane], v);
        v = v > 0.f ? v : 0.2f * v;
        v *= P3[lane];
    }
    #pragma unroll
    for (int off = 8; off; off >>= 1) v += __shfl_down_sync(0xffffffffu, v, off);
    if (lane == 0) out[warp] = v + pb3[0];
}

// ====================== host ======================

extern "C" void kernel_launch(void* const* d_in, const int* in_sizes, int n_in,
                              void* d_out, int out_size) {
    const float* x       = (const float*)d_in[0];
    const int*   src     = (const int*)d_in[1];
    const int*   dst     = (const int*)d_in[2];
    const float* w_edge  = (const float*)d_in[3];
    const int*   pos_src = (const int*)d_in[4];
    const int*   pos_dst = (const int*)d_in[5];
    const int*   neg_src = (const int*)d_in[6];
    const int*   neg_dst = (const int*)d_in[7];
    const float* W1 = (const float*)d_in[8];
    const float* b1 = (const float*)d_in[9];
    const float* W2 = (const float*)d_in[10];
    const float* b2 = (const float*)d_in[11];
    const float* W3 = (const float*)d_in[12];
    const float* b3 = (const float*)d_in[13];
    const float* P1 = (const float*)d_in[14];
    const float* pb1 = (const float*)d_in[15];
    const float* P2 = (const float*)d_in[16];
    const float* pb2 = (const float*)d_in[17];
    const float* P3 = (const float*)d_in[18];
    const float* pb3 = (const float*)d_in[19];
    float* out = (float*)d_out;

    void *p_x16, *p_hop1, *p_hop2, *p_hop3, *p_hA, *p_hB, *p_g;
    void *p_w1, *p_w2, *p_w3;
    cudaGetSymbolAddress(&p_x16,  g_x16);
    cudaGetSymbolAddress(&p_hop1, g_hop1);
    cudaGetSymbolAddress(&p_hop2, g_hop2);
    cudaGetSymbolAddress(&p_hop3, g_hop3);
    cudaGetSymbolAddress(&p_hA,   g_hA);
    cudaGetSymbolAddress(&p_hB,   g_hB);
    cudaGetSymbolAddress(&p_g,    g_g);
    cudaGetSymbolAddress(&p_w1,   g_wt1);
    cudaGetSymbolAddress(&p_w2,   g_wt2);
    cudaGetSymbolAddress(&p_w3,   g_wt3);
    __half* x16  = (__half*)p_x16;
    __half* hop1 = (__half*)p_hop1;
    __half* hop2 = (__half*)p_hop2;
    __half* hop3 = (__half*)p_hop3;
    __half* hA   = (__half*)p_hA;
    __half* hB   = (__half*)p_hB;
    __half* gg   = (__half*)p_g;
    __half* w1   = (__half*)p_w1;
    __half* w2   = (__half*)p_w2;
    __half* w3   = (__half*)p_w3;
    float* hfin = out + 2 * PP;

    const int EB = (EE + 255) / 256;
    const int WG = (NN * 32 + 255) / 256;
    const int MT = (NN + 127) / 128;

    // preprocessing
    k_prepall<<<(NN * 32 + 255) / 256, 256>>>(x, W1, W2, W3);
    k_hist<<<EB, 256>>>(dst);
    k_scanchain<<<(NN + 1023) / 1024, 1024>>>();
    k_scatter<<<EB, 256>>>(src, dst, w_edge);

    // layer 1
    k_spmmh<<<WG, 256>>>(x16, hop1);
    k_spmmh<<<WG, 256>>>(hop1, hop2);
    k_spmmh<<<WG, 256>>>(hop2, hop3);
    k_mgemm<512, 0><<<dim3(MT, 1), 256>>>(x16, hop1, hop2, hop3, w1, b1, hA);
    // layer 2
    k_spmmh<<<WG, 256>>>(hA, hop1);
    k_spmmh<<<WG, 256>>>(hop1, hop2);
    k_spmmh<<<WG, 256>>>(hop2, hop3);
    k_mgemm<512, 0><<<dim3(MT, 1), 256>>>(hA, hop1, hop2, hop3, w2, b2, hB);
    // layer 3 (Horner)
    k_mgemm<128, 1><<<dim3(MT, 2), 256>>>(hB, hB, hB, hB, w3, b3, gg);
    k_spmm64h<0><<<WG, 256>>>(gg + 192, 256, gg + 128, 256, hop1, 64);
    k_spmm64h<0><<<WG, 256>>>(hop1, 64,    gg + 64,  256, hop2, 64);
    k_spmm64h<1><<<WG, 256>>>(hop2, 64,    gg,       256, hfin, 64);

    // predictor
    k_pred<<<(2 * PP) / 8, 256>>>(pos_src, pos_dst, neg_src, neg_dst, hfin,
                                  P1, pb1, P2, pb2, P3, pb3, out);
}

// round 16
// speedup vs baseline: 1.1672x; 1.0174x over previous
#include <cuda_runtime.h>
#include <cuda_bf16.h>
#include <cuda_fp16.h>
#include <math.h>
#include <cstdint>

#define NN   50000
#define EE   800000
#define PP   65536
#define LDA  40

// ====================== scratch ======================

__device__ int    g_deg[NN];
__device__ int    g_fill[NN];
__device__ volatile int g_chain[64];
__device__ float2 g_dn2[NN];              // {dn, 1/dn}
__device__ int    g_rp[NN + 1];
__device__ __align__(16) int2 g_csr[EE];  // (src, w_edge bits) — NO dn folded
__device__ __align__(16) __half g_x16 [NN * 128];   // u0 = dn*x
__device__ __align__(16) __half g_hop1[NN * 128];
__device__ __align__(16) __half g_hop2[NN * 128];
__device__ __align__(16) __half g_hop3[NN * 128];
__device__ __align__(16) __half g_hA  [NN * 128];
__device__ __align__(16) __half g_hB  [NN * 128];
__device__ __align__(16) __half g_g   [NN * 256];
__device__ __align__(16) __half g_wt1[65536];
__device__ __align__(16) __half g_wt2[65536];
__device__ __align__(16) __half g_wt3[32768];

// ====================== helpers ======================

__device__ __forceinline__ uint32_t smem_u32(const void* p) {
    uint32_t a;
    asm("{ .reg .u64 t; cvta.to.shared.u64 t, %1; cvt.u32.u64 %0, t; }" : "=r"(a) : "l"(p));
    return a;
}

__device__ __forceinline__ void ldsm4(uint32_t* r, uint32_t addr) {
    asm volatile("ldmatrix.sync.aligned.m8n8.x4.shared.b16 {%0,%1,%2,%3}, [%4];"
                 : "=r"(r[0]), "=r"(r[1]), "=r"(r[2]), "=r"(r[3]) : "r"(addr));
}

__device__ __forceinline__ void mma16816f(float* c, const uint32_t* a, const uint32_t* b) {
    asm volatile(
        "mma.sync.aligned.m16n8k16.row.col.f32.f16.f16.f32 "
        "{%0,%1,%2,%3}, {%4,%5,%6,%7}, {%8,%9}, {%0,%1,%2,%3};"
        : "+f"(c[0]), "+f"(c[1]), "+f"(c[2]), "+f"(c[3])
        : "r"(a[0]), "r"(a[1]), "r"(a[2]), "r"(a[3]), "r"(b[0]), "r"(b[1]));
}

__device__ __forceinline__ void cpasync16(uint32_t saddr, const void* gptr) {
    asm volatile("cp.async.cg.shared.global [%0], [%1], 16;" :: "r"(saddr), "l"(gptr));
}
__device__ __forceinline__ void cpasync_commit() {
    asm volatile("cp.async.commit_group;" ::: "memory");
}
template <int N>
__device__ __forceinline__ void cpasync_wait() {
    asm volatile("cp.async.wait_group %0;" :: "n"(N) : "memory");
}

// ====================== launch 1: zero + weight transpose/convert ===========

__global__ void k_prepw(const float* __restrict__ W1, const float* __restrict__ W2,
                        const float* __restrict__ W3) {
    int gid = blockIdx.x * 256 + threadIdx.x;
    if (gid < NN) { g_deg[gid] = 0; g_fill[gid] = 0; }
    if (gid < 64) g_chain[gid] = 0;
    if (gid < 65536) {
        int n = gid >> 9, k = gid & 511;
        g_wt1[gid] = __float2half_rn(W1[k * 128 + n]);
    } else if (gid < 131072) {
        int idx = gid - 65536;
        int n = idx >> 9, k = idx & 511;
        g_wt2[idx] = __float2half_rn(W2[k * 128 + n]);
    } else if (gid < 163840) {
        int idx = gid - 131072;
        int r = idx >> 7, k = idx & 127;
        int j = r >> 6, n = r & 63;
        g_wt3[idx] = __float2half_rn(W3[(j * 128 + k) * 64 + n]);
    }
}

// ====================== launch 2: degree histogram ======================

__global__ void k_hist(const int* __restrict__ dst) {
    int e = blockIdx.x * blockDim.x + threadIdx.x;
    if (e < EE) atomicAdd(&g_deg[dst[e]], 1);
}

// ====================== launch 3: single-pass chained scan + dn ============

__global__ void __launch_bounds__(1024)
k_scanchain() {
    __shared__ int s[1024];
    __shared__ int sprev;
    int b = blockIdx.x;
    int i = b * 1024 + threadIdx.x;
    int v = (i < NN) ? g_deg[i] : 0;
    s[threadIdx.x] = v;
    __syncthreads();
    #pragma unroll
    for (int off = 1; off < 1024; off <<= 1) {
        int t = (threadIdx.x >= off) ? s[threadIdx.x - off] : 0;
        __syncthreads();
        s[threadIdx.x] += t;
        __syncthreads();
    }
    if (threadIdx.x == 0) {
        int prev = 0;
        if (b > 0) {
            int t;
            do { t = g_chain[b - 1]; } while (t == 0);
            prev = t - 1;
        }
        sprev = prev;
        __threadfence();
        g_chain[b] = prev + s[1023] + 1;
    }
    __syncthreads();
    int prev = sprev;
    if (i < NN) {
        g_rp[i + 1] = s[threadIdx.x] + prev;
        if (i == 0) g_rp[0] = 0;
        int d = (v < 1) ? 1 : v;
        float df = (float)d;
        g_dn2[i] = make_float2(rsqrtf(df), sqrtf(df));
    }
}

// ====================== launch 4: scatter CSR + x -> u0 fp16 ================

__global__ void k_scatxcvt(const int* __restrict__ src, const int* __restrict__ dst,
                           const float* __restrict__ w, const float* __restrict__ x) {
    int gid = blockIdx.x * blockDim.x + threadIdx.x;
    if (gid < EE) {
        int s = src[gid], d = dst[gid];
        int slot = g_rp[d] + atomicAdd(&g_fill[d], 1);
        g_csr[slot] = make_int2(s, __float_as_int(w[gid]));
    }
    if (gid < NN * 32) {
        int row = gid >> 5;
        float dn = g_dn2[row].x;
        float4 v = __ldg((const float4*)x + gid);
        __half2 a = __floats2half2_rn(v.x * dn, v.y * dn);
        __half2 b = __floats2half2_rn(v.z * dn, v.w * dn);
        ((uint2*)g_x16)[gid] = make_uint2(*(uint32_t*)&a, *(uint32_t*)&b);
    }
}

// ====================== SpMM width 128, half-warp paired gather =============
// lanes 0-15 = edge e, lanes 16-31 = edge e+1; lane covers 8 elements (uint4).
// u_out[d] = dn[d]^2 * sum_e w_e * u_in[src]

__global__ void __launch_bounds__(256)
k_spmmh(const __half* __restrict__ fin, __half* __restrict__ fout) {
    int gw = (blockIdx.x * blockDim.x + threadIdx.x) >> 5;
    int lane = threadIdx.x & 31;
    if (gw >= NN) return;
    int hw = lane >> 4, sl = lane & 15;
    int beg = g_rp[gw], end = g_rp[gw + 1];
    const uint4* in = (const uint4*)fin;
    float f0 = 0.f, f1 = 0.f, f2 = 0.f, f3 = 0.f;
    float f4 = 0.f, f5 = 0.f, f6 = 0.f, f7 = 0.f;
    int e = beg;
    for (; e + 4 <= end; e += 4) {
        int2 pa = __ldg(&g_csr[e + hw]);
        int2 pb = __ldg(&g_csr[e + 2 + hw]);
        uint4 va = __ldg(&in[(size_t)pa.x * 16 + sl]);
        uint4 vb = __ldg(&in[(size_t)pb.x * 16 + sl]);
        float wa = __int_as_float(pa.y);
        float wb = __int_as_float(pb.y);
        float2 c;
        c = __half22float2(*(__half2*)&va.x); f0 = fmaf(wa, c.x, f0); f1 = fmaf(wa, c.y, f1);
        c = __half22float2(*(__half2*)&va.y); f2 = fmaf(wa, c.x, f2); f3 = fmaf(wa, c.y, f3);
        c = __half22float2(*(__half2*)&va.z); f4 = fmaf(wa, c.x, f4); f5 = fmaf(wa, c.y, f5);
        c = __half22float2(*(__half2*)&va.w); f6 = fmaf(wa, c.x, f6); f7 = fmaf(wa, c.y, f7);
        c = __half22float2(*(__half2*)&vb.x); f0 = fmaf(wb, c.x, f0); f1 = fmaf(wb, c.y, f1);
        c = __half22float2(*(__half2*)&vb.y); f2 = fmaf(wb, c.x, f2); f3 = fmaf(wb, c.y, f3);
        c = __half22float2(*(__half2*)&vb.z); f4 = fmaf(wb, c.x, f4); f5 = fmaf(wb, c.y, f5);
        c = __half22float2(*(__half2*)&vb.w); f6 = fmaf(wb, c.x, f6); f7 = fmaf(wb, c.y, f7);
    }
    for (; e + 2 <= end; e += 2) {
        int2 p = __ldg(&g_csr[e + hw]);
        uint4 v = __ldg(&in[(size_t)p.x * 16 + sl]);
        float w = __int_as_float(p.y);
        float2 c;
        c = __half22float2(*(__half2*)&v.x); f0 = fmaf(w, c.x, f0); f1 = fmaf(w, c.y, f1);
        c = __half22float2(*(__half2*)&v.y); f2 = fmaf(w, c.x, f2); f3 = fmaf(w, c.y, f3);
        c = __half22float2(*(__half2*)&v.z); f4 = fmaf(w, c.x, f4); f5 = fmaf(w, c.y, f5);
        c = __half22float2(*(__half2*)&v.w); f6 = fmaf(w, c.x, f6); f7 = fmaf(w, c.y, f7);
    }
    if (e < end) {
        int2 p = __ldg(&g_csr[e]);
        uint4 v = __ldg(&in[(size_t)p.x * 16 + sl]);
        float w = hw ? 0.f : __int_as_float(p.y);
        float2 c;
        c = __half22float2(*(__half2*)&v.x); f0 = fmaf(w, c.x, f0); f1 = fmaf(w, c.y, f1);
        c = __half22float2(*(__half2*)&v.y); f2 = fmaf(w, c.x, f2); f3 = fmaf(w, c.y, f3);
        c = __half22float2(*(__half2*)&v.z); f4 = fmaf(w, c.x, f4); f5 = fmaf(w, c.y, f5);
        c = __half22float2(*(__half2*)&v.w); f6 = fmaf(w, c.x, f6); f7 = fmaf(w, c.y, f7);
    }
    f0 += __shfl_xor_sync(0xffffffffu, f0, 16);
    f1 += __shfl_xor_sync(0xffffffffu, f1, 16);
    f2 += __shfl_xor_sync(0xffffffffu, f2, 16);
    f3 += __shfl_xor_sync(0xffffffffu, f3, 16);
    f4 += __shfl_xor_sync(0xffffffffu, f4, 16);
    f5 += __shfl_xor_sync(0xffffffffu, f5, 16);
    f6 += __shfl_xor_sync(0xffffffffu, f6, 16);
    f7 += __shfl_xor_sync(0xffffffffu, f7, 16);
    if (hw == 0) {
        float dn = g_dn2[gw].x;
        float dn2 = dn * dn;
        __half2 h0 = __floats2half2_rn(f0 * dn2, f1 * dn2);
        __half2 h1 = __floats2half2_rn(f2 * dn2, f3 * dn2);
        __half2 h2 = __floats2half2_rn(f4 * dn2, f5 * dn2);
        __half2 h3 = __floats2half2_rn(f6 * dn2, f7 * dn2);
        uint4 o;
        o.x = *(uint32_t*)&h0; o.y = *(uint32_t*)&h1;
        o.z = *(uint32_t*)&h2; o.w = *(uint32_t*)&h3;
        ((uint4*)fout)[(size_t)gw * 16 + sl] = o;
    }
}

// ====================== SpMM width 64, half-warp, fused add =================
// FINAL=0: u_out = dn^2 * sum + u_add (fp16)
// FINAL=1: h = dn * sum + (1/dn) * u_add (fp32)

template <int FINAL>
__global__ void __launch_bounds__(256)
k_spmm64h(const __half* __restrict__ fin, int sIn,
          const __half* __restrict__ addv, int sAdd,
          void* __restrict__ fout, int sOut) {
    int gw = (blockIdx.x * blockDim.x + threadIdx.x) >> 5;
    int lane = threadIdx.x & 31;
    if (gw >= NN) return;
    int hw = lane >> 4, sl = lane & 15;
    int beg = g_rp[gw], end = g_rp[gw + 1];
    float f0 = 0.f, f1 = 0.f, f2 = 0.f, f3 = 0.f;
    int e = beg;
    for (; e + 4 <= end; e += 4) {
        int2 pa = __ldg(&g_csr[e + hw]);
        int2 pb = __ldg(&g_csr[e + 2 + hw]);
        uint2 va = __ldg((const uint2*)(fin + (size_t)pa.x * sIn) + sl);
        uint2 vb = __ldg((const uint2*)(fin + (size_t)pb.x * sIn) + sl);
        float wa = __int_as_float(pa.y);
        float wb = __int_as_float(pb.y);
        float2 c;
        c = __half22float2(*(__half2*)&va.x); f0 = fmaf(wa, c.x, f0); f1 = fmaf(wa, c.y, f1);
        c = __half22float2(*(__half2*)&va.y); f2 = fmaf(wa, c.x, f2); f3 = fmaf(wa, c.y, f3);
        c = __half22float2(*(__half2*)&vb.x); f0 = fmaf(wb, c.x, f0); f1 = fmaf(wb, c.y, f1);
        c = __half22float2(*(__half2*)&vb.y); f2 = fmaf(wb, c.x, f2); f3 = fmaf(wb, c.y, f3);
    }
    for (; e + 2 <= end; e += 2) {
        int2 p = __ldg(&g_csr[e + hw]);
        uint2 v = __ldg((const uint2*)(fin + (size_t)p.x * sIn) + sl);
        float w = __int_as_float(p.y);
        float2 c;
        c = __half22float2(*(__half2*)&v.x); f0 = fmaf(w, c.x, f0); f1 = fmaf(w, c.y, f1);
        c = __half22float2(*(__half2*)&v.y); f2 = fmaf(w, c.x, f2); f3 = fmaf(w, c.y, f3);
    }
    if (e < end) {
        int2 p = __ldg(&g_csr[e]);
        uint2 v = __ldg((const uint2*)(fin + (size_t)p.x * sIn) + sl);
        float w = hw ? 0.f : __int_as_float(p.y);
        float2 c;
        c = __half22float2(*(__half2*)&v.x); f0 = fmaf(w, c.x, f0); f1 = fmaf(w, c.y, f1);
        c = __half22float2(*(__half2*)&v.y); f2 = fmaf(w, c.x, f2); f3 = fmaf(w, c.y, f3);
    }
    f0 += __shfl_xor_sync(0xffffffffu, f0, 16);
    f1 += __shfl_xor_sync(0xffffffffu, f1, 16);
    f2 += __shfl_xor_sync(0xffffffffu, f2, 16);
    f3 += __shfl_xor_sync(0xffffffffu, f3, 16);
    if (hw == 0) {
        float2 dd = g_dn2[gw];
        uint2 av = __ldg((const uint2*)(addv + (size_t)gw * sAdd) + sl);
        float2 a0 = __half22float2(*(__half2*)&av.x);
        float2 a1 = __half22float2(*(__half2*)&av.y);
        if (FINAL) {
            float4 o;
            o.x = dd.x * f0 + dd.y * a0.x;
            o.y = dd.x * f1 + dd.y * a0.y;
            o.z = dd.x * f2 + dd.y * a1.x;
            o.w = dd.x * f3 + dd.y * a1.y;
            ((float4*)((float*)fout + (size_t)gw * sOut))[sl] = o;
        } else {
            float dn2 = dd.x * dd.x;
            __half2 h0 = __floats2half2_rn(dn2 * f0 + a0.x, dn2 * f1 + a0.y);
            __half2 h1 = __floats2half2_rn(dn2 * f2 + a1.x, dn2 * f3 + a1.y);
            ((uint2*)((__half*)fout + (size_t)gw * sOut))[sl] =
                make_uint2(*(uint32_t*)&h0, *(uint32_t*)&h1);
        }
    }
}

// ====================== fp16 HMMA GEMM, cp.async 2-stage pipeline ==========
// A planes are u-scale; epilogue: MODE 0: out = relu(acc + dn[r]*bias[c]) (u-scale)
// MODE 1: out[r*256+by*128+c] = acc + (col<64 ? dn[r]*bias[col] : 0) (u-scale)

template <int KTOT, int MODE>
__global__ void __launch_bounds__(256, 1)
k_mgemm(const __half* __restrict__ f0, const __half* __restrict__ f1,
        const __half* __restrict__ f2, const __half* __restrict__ f3,
        const __half* __restrict__ Wt,
        const float* __restrict__ bias, __half* __restrict__ out) {
    __shared__ __half As[2][128 * LDA];
    __shared__ __half Bs[2][128 * LDA];

    const __half* bases[4] = {f0, f1, f2, f3};
    int tid = threadIdx.x, warp = tid >> 5, lane = tid & 31;
    int mw = warp & 1, nw = warp >> 1;
    int row0 = blockIdx.x * 128;
    int rbase = (MODE == 1) ? blockIdx.y * 128 : 0;

    int ar0 = tid >> 2, aj0 = tid & 3;
    int ar1 = (tid + 256) >> 2, aj1 = tid & 3;

    float acc[4][4][4];
    #pragma unroll
    for (int i = 0; i < 4; i++)
        #pragma unroll
        for (int j = 0; j < 4; j++)
            #pragma unroll
            for (int q = 0; q < 4; q++) acc[i][j][q] = 0.f;

    const int NSTEP = KTOT / 32;

    auto load_stage = [&](int buf, int s) {
        const __half* Ab = bases[(s * 32) >> 7];
        int coloff = (s * 32) & 127;
        uint32_t sA = smem_u32(&As[buf][0]);
        uint32_t sB = smem_u32(&Bs[buf][0]);
        int g0 = row0 + ar0; if (g0 > NN - 1) g0 = NN - 1;
        int g1 = row0 + ar1; if (g1 > NN - 1) g1 = NN - 1;
        cpasync16(sA + (uint32_t)(ar0 * LDA + aj0 * 8) * 2,
                  Ab + (size_t)g0 * 128 + coloff + aj0 * 8);
        cpasync16(sA + (uint32_t)(ar1 * LDA + aj1 * 8) * 2,
                  Ab + (size_t)g1 * 128 + coloff + aj1 * 8);
        cpasync16(sB + (uint32_t)(ar0 * LDA + aj0 * 8) * 2,
                  Wt + (size_t)(rbase + ar0) * KTOT + s * 32 + aj0 * 8);
        cpasync16(sB + (uint32_t)(ar1 * LDA + aj1 * 8) * 2,
                  Wt + (size_t)(rbase + ar1) * KTOT + s * 32 + aj1 * 8);
    };

    load_stage(0, 0);
    cpasync_commit();

    #pragma unroll 1
    for (int s = 0; s < NSTEP; s++) {
        int buf = s & 1;
        cpasync_wait<0>();
        __syncthreads();
        if (s + 1 < NSTEP) {
            load_stage(buf ^ 1, s + 1);
            cpasync_commit();
        }

        uint32_t sA = smem_u32(&As[buf][0]);
        uint32_t sB = smem_u32(&Bs[buf][0]);
        #pragma unroll
        for (int kk = 0; kk < 2; kk++) {
            int akoff = kk * 16 + ((lane >> 4) << 3);
            int lrow = lane & 15;
            uint32_t a[4][4];
            #pragma unroll
            for (int fi = 0; fi < 4; fi++) {
                uint32_t off = (uint32_t)(((64 * mw + 16 * fi + lrow) * LDA + akoff) * 2);
                ldsm4(a[fi], sA + off);
            }
            uint32_t b[4][2];
            #pragma unroll
            for (int fj2 = 0; fj2 < 2; fj2++) {
                uint32_t off = (uint32_t)(((32 * nw + 16 * fj2 + lrow) * LDA + akoff) * 2);
                uint32_t t[4];
                ldsm4(t, sB + off);
                b[2 * fj2][0] = t[0]; b[2 * fj2][1] = t[2];
                b[2 * fj2 + 1][0] = t[1]; b[2 * fj2 + 1][1] = t[3];
            }
            #pragma unroll
            for (int fi = 0; fi < 4; fi++)
                #pragma unroll
                for (int fj = 0; fj < 4; fj++)
                    mma16816f(acc[fi][fj], a[fi], b[fj]);
        }
        __syncthreads();
    }

    #pragma unroll
    for (int fi = 0; fi < 4; fi++) {
        #pragma unroll
        for (int fj = 0; fj < 4; fj++) {
            int mrow = row0 + 64 * mw + 16 * fi + (lane >> 2);
            int col  = 32 * nw + 8 * fj + 2 * (lane & 3);
            #pragma unroll
            for (int h = 0; h < 2; h++) {
                int r = mrow + 8 * h;
                if (r < NN) {
                    float dnr = g_dn2[r].x;
                    float v0 = acc[fi][fj][2 * h + 0];
                    float v1 = acc[fi][fj][2 * h + 1];
                    if (MODE == 0) {
                        v0 += dnr * bias[col];
                        v1 += dnr * bias[col + 1];
                        v0 = v0 > 0.f ? v0 : 0.f;
                        v1 = v1 > 0.f ? v1 : 0.f;
                        *(__half2*)(out + (size_t)r * 128 + col) = __floats2half2_rn(v0, v1);
                    } else {
                        int cg = blockIdx.y * 128 + col;
                        if (cg < 64) { v0 += dnr * bias[cg]; v1 += dnr * bias[cg + 1]; }
                        *(__half2*)(out + (size_t)r * 256 + cg) = __floats2half2_rn(v0, v1);
                    }
                }
            }
        }
    }
}

// ====================== predictor MLP ======================

__global__ void __launch_bounds__(256)
k_pred(const int* __restrict__ ps, const int* __restrict__ pd,
       const int* __restrict__ ns, const int* __restrict__ nd,
       const float* __restrict__ h,
       const float* __restrict__ P1, const float* __restrict__ pb1,
       const float* __restrict__ P2, const float* __restrict__ pb2,
       const float* __restrict__ P3, const float* __restrict__ pb3,
       float* __restrict__ out) {
    __shared__ float zs[8][64];
    __shared__ float a1s[8][32];
    int warp = (blockIdx.x * blockDim.x + threadIdx.x) >> 5;
    int lane = threadIdx.x & 31;
    int wl   = (threadIdx.x >> 5) & 7;
    if (warp >= 2 * PP) return;
    int s, d;
    if (warp < PP) { s = ps[warp]; d = pd[warp]; }
    else           { s = ns[warp - PP]; d = nd[warp - PP]; }

    const float* hs = h + (size_t)s * 64;
    const float* hd = h + (size_t)d * 64;
    zs[wl][lane]      = hs[lane]      * hd[lane];
    zs[wl][lane + 32] = hs[lane + 32] * hd[lane + 32];
    __syncwarp();

    float a = pb1[lane];
    #pragma unroll
    for (int k = 0; k < 64; k++) a = fmaf(zs[wl][k], P1[k * 32 + lane], a);
    a = a > 0.f ? a : 0.2f * a;
    a1s[wl][lane] = a;
    __syncwarp();

    float v = 0.f;
    if (lane < 16) {
        v = pb2[lane];
        #pragma unroll
        for (int k = 0; k < 32; k++) v = fmaf(a1s[wl][k], P2[k * 16 + lane], v);
        v = v > 0.f ? v : 0.2f * v;
        v *= P3[lane];
    }
    #pragma unroll
    for (int off = 8; off; off >>= 1) v += __shfl_down_sync(0xffffffffu, v, off);
    if (lane == 0) out[warp] = v + pb3[0];
}

// ====================== host ======================

extern "C" void kernel_launch(void* const* d_in, const int* in_sizes, int n_in,
                              void* d_out, int out_size) {
    const float* x       = (const float*)d_in[0];
    const int*   src     = (const int*)d_in[1];
    const int*   dst     = (const int*)d_in[2];
    const float* w_edge  = (const float*)d_in[3];
    const int*   pos_src = (const int*)d_in[4];
    const int*   pos_dst = (const int*)d_in[5];
    const int*   neg_src = (const int*)d_in[6];
    const int*   neg_dst = (const int*)d_in[7];
    const float* W1 = (const float*)d_in[8];
    const float* b1 = (const float*)d_in[9];
    const float* W2 = (const float*)d_in[10];
    const float* b2 = (const float*)d_in[11];
    const float* W3 = (const float*)d_in[12];
    const float* b3 = (const float*)d_in[13];
    const float* P1 = (const float*)d_in[14];
    const float* pb1 = (const float*)d_in[15];
    const float* P2 = (const float*)d_in[16];
    const float* pb2 = (const float*)d_in[17];
    const float* P3 = (const float*)d_in[18];
    const float* pb3 = (const float*)d_in[19];
    float* out = (float*)d_out;

    void *p_x16, *p_hop1, *p_hop2, *p_hop3, *p_hA, *p_hB, *p_g;
    void *p_w1, *p_w2, *p_w3;
    cudaGetSymbolAddress(&p_x16,  g_x16);
    cudaGetSymbolAddress(&p_hop1, g_hop1);
    cudaGetSymbolAddress(&p_hop2, g_hop2);
    cudaGetSymbolAddress(&p_hop3, g_hop3);
    cudaGetSymbolAddress(&p_hA,   g_hA);
    cudaGetSymbolAddress(&p_hB,   g_hB);
    cudaGetSymbolAddress(&p_g,    g_g);
    cudaGetSymbolAddress(&p_w1,   g_wt1);
    cudaGetSymbolAddress(&p_w2,   g_wt2);
    cudaGetSymbolAddress(&p_w3,   g_wt3);
    __half* x16  = (__half*)p_x16;
    __half* hop1 = (__half*)p_hop1;
    __half* hop2 = (__half*)p_hop2;
    __half* hop3 = (__half*)p_hop3;
    __half* hA   = (__half*)p_hA;
    __half* hB   = (__half*)p_hB;
    __half* gg   = (__half*)p_g;
    __half* w1   = (__half*)p_w1;
    __half* w2   = (__half*)p_w2;
    __half* w3   = (__half*)p_w3;
    float* hfin = out + 2 * PP;

    const int EB = (EE + 255) / 256;
    const int WG = (NN * 32 + 255) / 256;
    const int MT = (NN + 127) / 128;
    const int SCB = (NN * 32 + 255) / 256;   // covers EE too (1.6M > 800k)

    // preprocessing (4 launches)
    k_prepw<<<(163840 + 255) / 256, 256>>>(W1, W2, W3);
    k_hist<<<EB, 256>>>(dst);
    k_scanchain<<<(NN + 1023) / 1024, 1024>>>();
    k_scatxcvt<<<SCB, 256>>>(src, dst, w_edge, x);

    // layer 1
    k_spmmh<<<WG, 256>>>(x16, hop1);
    k_spmmh<<<WG, 256>>>(hop1, hop2);
    k_spmmh<<<WG, 256>>>(hop2, hop3);
    k_mgemm<512, 0><<<dim3(MT, 1), 256>>>(x16, hop1, hop2, hop3, w1, b1, hA);
    // layer 2
    k_spmmh<<<WG, 256>>>(hA, hop1);
    k_spmmh<<<WG, 256>>>(hop1, hop2);
    k_spmmh<<<WG, 256>>>(hop2, hop3);
    k_mgemm<512, 0><<<dim3(MT, 1), 256>>>(hA, hop1, hop2, hop3, w2, b2, hB);
    // layer 3 (Horner, u-space)
    k_mgemm<128, 1><<<dim3(MT, 2), 256>>>(hB, hB, hB, hB, w3, b3, gg);
    k_spmm64h<0><<<WG, 256>>>(gg + 192, 256, gg + 128, 256, hop1, 64);
    k_spmm64h<0><<<WG, 256>>>(hop1, 64,    gg + 64,  256, hop2, 64);
    k_spmm64h<1><<<WG, 256>>>(hop2, 64,    gg,       256, hfin, 64);

    // predictor
    k_pred<<<(2 * PP) / 8, 256>>>(pos_src, pos_dst, neg_src, neg_dst, hfin,
                                  P1, pb1, P2, pb2, P3, pb3, out);
}